// round 5
// baseline (speedup 1.0000x reference)
#include <cuda_runtime.h>

// EMA gated decomposition:
//   trend[b,0,c] = x[b,0,c]
//   trend[b,t,c] = 0.7*x[b,t,c] + 0.3*trend[b,t-1,c]
//   out = g*x + (1-2g)*trend,  g = clip(gate,0,1)
//
// R3: SEG 128->64 (262144 threads, ~55 warps/SM) and LOOKBACK 16->12
// (0.3^12 ~ 5.3e-7 rel carry error). Traffic +3.0% vs R2 for 2x occupancy.

#define B_DIM 32
#define L_DIM 4096
#define C_DIM 512
#define C4    (C_DIM / 4)     // 128 float4 per (b,t) row
#define SEG   64
#define NSEG  (L_DIM / SEG)   // 64
#define LOOKBACK 12

__global__ __launch_bounds__(256) void ema_gate_kernel(
    const float4* __restrict__ x,
    const float*  __restrict__ gate,
    float4* __restrict__ out)
{
    int tid = blockIdx.x * blockDim.x + threadIdx.x;   // 0 .. 262143
    int c4  = tid & (C4 - 1);          // channel group (fastest -> coalesced)
    int rs  = tid >> 7;                // (b, seg)
    int seg = rs & (NSEG - 1);
    int b   = rs >> 6;

    float g  = fminf(fmaxf(*gate, 0.0f), 1.0f);
    float w1 = g;                 // coeff of x
    float w2 = 1.0f - 2.0f * g;   // coeff of trend
    const float AL = 0.7f, BE = 0.3f;

    int base = (b * L_DIM) * C4 + c4;
    int tstart = seg * SEG;
    int tend   = tstart + SEG;

    float4 h;
    int t;
    if (seg == 0) {
        // exact start: trend[0] = x[0]
        float4 v = x[base];
        h = v;
        float4 o;
        o.x = fmaf(w2, h.x, w1 * v.x);
        o.y = fmaf(w2, h.y, w1 * v.y);
        o.z = fmaf(w2, h.z, w1 * v.z);
        o.w = fmaf(w2, h.w, w1 * v.w);
        out[base] = o;
        t = 1;
    } else {
        // warm-up: seed carry LOOKBACK steps back; 0.3^12 ~ 5.3e-7 rel error
        int t0 = tstart - LOOKBACK;
        h = x[base + t0 * C4];
        #pragma unroll
        for (int tw = t0 + 1; tw < tstart; ++tw) {
            float4 v = x[base + tw * C4];
            h.x = fmaf(AL, v.x, BE * h.x);
            h.y = fmaf(AL, v.y, BE * h.y);
            h.z = fmaf(AL, v.z, BE * h.z);
            h.w = fmaf(AL, v.w, BE * h.w);
        }
        t = tstart;
    }

    #pragma unroll 8
    for (; t < tend; ++t) {
        float4 v = x[base + t * C4];
        h.x = fmaf(AL, v.x, BE * h.x);
        h.y = fmaf(AL, v.y, BE * h.y);
        h.z = fmaf(AL, v.z, BE * h.z);
        h.w = fmaf(AL, v.w, BE * h.w);
        float4 o;
        o.x = fmaf(w2, h.x, w1 * v.x);
        o.y = fmaf(w2, h.y, w1 * v.y);
        o.z = fmaf(w2, h.z, w1 * v.z);
        o.w = fmaf(w2, h.w, w1 * v.w);
        out[base + t * C4] = o;
    }
}

extern "C" void kernel_launch(void* const* d_in, const int* in_sizes, int n_in,
                              void* d_out, int out_size)
{
    const float4* x    = (const float4*)d_in[0];
    const float*  gate = (const float*)d_in[1];
    float4* out        = (float4*)d_out;

    int total_threads = B_DIM * NSEG * C4;   // 262144
    int block = 256;
    int grid  = total_threads / block;       // 1024
    ema_gate_kernel<<<grid, block>>>(x, gate, out);
}

// round 6
// speedup vs baseline: 1.1148x; 1.1148x over previous
#include <cuda_runtime.h>

// EMA gated decomposition:
//   trend[b,0,c] = x[b,0,c]
//   trend[b,t,c] = 0.7*x[b,t,c] + 0.3*trend[b,t-1,c]
//   out = g*x + (1-2g)*trend,  g = clip(gate,0,1)
//
// R5: revert to SEG=128 (best geometry, R3's 2x-threads regressed DRAM eff).
// Force per-thread MLP=8: explicit batched loads of 8 float4 per block of 8
// rows, then recurrence+store. Uniform warm-up of exactly LOOKBACK iters by
// including the seed row in the recurrence (0.7v+0.3v ~= v to 1 ulp).

#define B_DIM 32
#define L_DIM 4096
#define C_DIM 512
#define C4    (C_DIM / 4)     // 128 float4 per (b,t) row
#define SEG   128
#define NSEG  (L_DIM / SEG)   // 32
#define LOOKBACK 16
#define BATCH 8

__global__ __launch_bounds__(256) void ema_gate_kernel(
    const float4* __restrict__ x,
    const float*  __restrict__ gate,
    float4* __restrict__ out)
{
    int tid = blockIdx.x * blockDim.x + threadIdx.x;   // 0 .. 131071
    int c4  = tid & (C4 - 1);          // channel group (fastest -> coalesced)
    int rs  = tid >> 7;                // (b, seg)
    int seg = rs & (NSEG - 1);
    int b   = rs >> 5;

    float g  = fminf(fmaxf(*gate, 0.0f), 1.0f);
    float w1 = g;                 // coeff of x
    float w2 = 1.0f - 2.0f * g;   // coeff of trend
    const float AL = 0.7f, BE = 0.3f;

    int base   = (b * L_DIM) * C4 + c4;
    int tstart = seg * SEG;
    int tend   = tstart + SEG;
    int t0     = (seg == 0) ? 0 : (tstart - LOOKBACK);

    // Seed: h = x[t0]. The recurrence then re-processes t0 itself:
    // 0.7*x[t0] + 0.3*x[t0] == x[t0] to 1 ulp, keeping loops 8-aligned.
    float4 h = x[base + t0 * C4];

    float4 vb[BATCH];

    // Warm-up (seg>0): exactly LOOKBACK iterations, no stores.
    for (int tb = t0; tb < tstart; tb += BATCH) {
        #pragma unroll
        for (int i = 0; i < BATCH; ++i)
            vb[i] = x[base + (tb + i) * C4];
        #pragma unroll
        for (int i = 0; i < BATCH; ++i) {
            h.x = fmaf(AL, vb[i].x, BE * h.x);
            h.y = fmaf(AL, vb[i].y, BE * h.y);
            h.z = fmaf(AL, vb[i].z, BE * h.z);
            h.w = fmaf(AL, vb[i].w, BE * h.w);
        }
    }

    // Main segment: blocks of 8 rows, loads front-batched.
    for (int tb = tstart; tb < tend; tb += BATCH) {
        #pragma unroll
        for (int i = 0; i < BATCH; ++i)
            vb[i] = x[base + (tb + i) * C4];
        #pragma unroll
        for (int i = 0; i < BATCH; ++i) {
            h.x = fmaf(AL, vb[i].x, BE * h.x);
            h.y = fmaf(AL, vb[i].y, BE * h.y);
            h.z = fmaf(AL, vb[i].z, BE * h.z);
            h.w = fmaf(AL, vb[i].w, BE * h.w);
            float4 o;
            o.x = fmaf(w2, h.x, w1 * vb[i].x);
            o.y = fmaf(w2, h.y, w1 * vb[i].y);
            o.z = fmaf(w2, h.z, w1 * vb[i].z);
            o.w = fmaf(w2, h.w, w1 * vb[i].w);
            out[base + (tb + i) * C4] = o;
        }
    }
}

extern "C" void kernel_launch(void* const* d_in, const int* in_sizes, int n_in,
                              void* d_out, int out_size)
{
    const float4* x    = (const float4*)d_in[0];
    const float*  gate = (const float*)d_in[1];
    float4* out        = (float4*)d_out;

    int total_threads = B_DIM * NSEG * C4;   // 131072
    int block = 256;
    int grid  = total_threads / block;       // 512
    ema_gate_kernel<<<grid, block>>>(x, gate, out);
}